// round 1
// baseline (speedup 1.0000x reference)
#include <cuda_runtime.h>
#include <math.h>

// ---------------------------------------------------------------------------
// Problem constants
//   B=2, T=64, N=128  -> TN = 8192 tokens/batch, M = 16384 total
//   IN_FEAT=2, H_LSTM=4, D=8, FH=FW=16, C_MAP=2048, C_COMP=32, TH=0.5, IMG=512
// ---------------------------------------------------------------------------
#define M_TOK   16384
#define TN      8192
#define KSPLIT  8
#define NCHUNK  32      // channel chunks for comp conv (2048/64)

// Scratch (no allocation allowed -> __device__ globals)
__device__ float g_comp_part[NCHUNK * 16384];      // per-chunk partial comp
__device__ float g_comp[16384];                    // [b][p=256][oc=32] channel-last
__device__ float g_Qn[M_TOK * 8];                  // NEGATED Q
__device__ float g_KV[M_TOK * 16];                 // K[8] | V[8] per token
__device__ float g_att[(size_t)KSPLIT * M_TOK * 8];// split-K partials

// ---------------------------------------------------------------------------
// K1: comp[b,oc,p] partials.  comp = metadata[b,c,p] . comp_w[oc,c]
// grid (NCHUNK, B), block 256 (one pixel per thread), 64 channels per block.
// ---------------------------------------------------------------------------
__global__ void __launch_bounds__(256) k_comp_partial(
    const float* __restrict__ metadata, const float* __restrict__ comp_w)
{
    const int chunk = blockIdx.x;
    const int b     = blockIdx.y;
    const int p     = threadIdx.x;
    const int c0    = chunk * 64;

    __shared__ float sw[32 * 64];   // [oc][cl]
    for (int idx = threadIdx.x; idx < 2048; idx += 256) {
        int oc = idx >> 6, cl = idx & 63;
        sw[idx] = comp_w[oc * 2048 + c0 + cl];
    }
    __syncthreads();

    float acc[32];
#pragma unroll
    for (int oc = 0; oc < 32; ++oc) acc[oc] = 0.f;

    const float* mp = metadata + ((size_t)b * 2048 + c0) * 256 + p;
#pragma unroll 4
    for (int cl = 0; cl < 64; ++cl) {
        float mv = __ldg(mp + cl * 256);            // coalesced across p
#pragma unroll
        for (int oc = 0; oc < 32; ++oc)
            acc[oc] = fmaf(mv, sw[oc * 64 + cl], acc[oc]);
    }

    float4* op = (float4*)(g_comp_part + (size_t)chunk * 16384 + (b * 256 + p) * 32);
#pragma unroll
    for (int i = 0; i < 8; ++i)
        op[i] = make_float4(acc[4*i], acc[4*i+1], acc[4*i+2], acc[4*i+3]);
}

// ---------------------------------------------------------------------------
// K1b: reduce the NCHUNK partials + bias -> g_comp  (deterministic, no atomics)
// ---------------------------------------------------------------------------
__global__ void __launch_bounds__(256) k_comp_reduce(const float* __restrict__ comp_b)
{
    int i = blockIdx.x * blockDim.x + threadIdx.x;   // 0..16383
    float s = __ldg(comp_b + (i & 31));
#pragma unroll 8
    for (int ch = 0; ch < NCHUNK; ++ch)
        s += g_comp_part[(size_t)ch * 16384 + i];
    g_comp[i] = s;
}

// ---------------------------------------------------------------------------
// K2: per-token pipeline -> Qn, K, V
// ---------------------------------------------------------------------------
__device__ __forceinline__ float sigf(float x) { return 1.f / (1.f + expf(-x)); }

__global__ void __launch_bounds__(256) k_qkv(
    const float* __restrict__ x,
    const float* __restrict__ w_ih, const float* __restrict__ b_ih,
    const float* __restrict__ b_hh,
    const float* __restrict__ fc_w,  const float* __restrict__ fc_b,
    const float* __restrict__ fc2_w, const float* __restrict__ fc2_b,
    const float* __restrict__ fc3_w, const float* __restrict__ fc3_b,
    const float* __restrict__ vf_w,  const float* __restrict__ vf_b)
{
    const int m = blockIdx.x * blockDim.x + threadIdx.x;   // 0..16383
    const int b = m >> 13;
    const int q = m & 8191;
    const int t = q >> 7;

    const float px = __ldg(x + b * 16384 + q);           // x[b,0,t,n]
    const float py = __ldg(x + b * 16384 + 8192 + q);    // x[b,1,t,n]

    // positional encoding: c=2 -> div = exp(0) = 1 -> pe = (sin t, cos t)
    const float xr0 = px + sinf((float)t);
    const float xr1 = py + cosf((float)t);

    // single-step LSTM, h0=c0=0; gate order i,f,g,o (f unused since c0=0)
    float Xl[4];
#pragma unroll
    for (int j = 0; j < 4; ++j) {
        float gi = __ldg(w_ih + 2*j)        * xr0 + __ldg(w_ih + 2*j+1)        * xr1 + __ldg(b_ih + j)      + __ldg(b_hh + j);
        float gg = __ldg(w_ih + 2*(8+j))    * xr0 + __ldg(w_ih + 2*(8+j)+1)    * xr1 + __ldg(b_ih + 8 + j)  + __ldg(b_hh + 8 + j);
        float go = __ldg(w_ih + 2*(12+j))   * xr0 + __ldg(w_ih + 2*(12+j)+1)   * xr1 + __ldg(b_ih + 12 + j) + __ldg(b_hh + 12 + j);
        float cst = sigf(gi) * tanhf(gg);
        Xl[j] = sigf(go) * tanhf(cst);
    }

    // bilinear grid-sample of g_comp at (px/32 - 0.5, py/32 - 0.5), zero pad
    const float ix = px * (1.f / 32.f) - 0.5f;
    const float iy = py * (1.f / 32.f) - 0.5f;
    const float fx0 = floorf(ix), fy0 = floorf(iy);
    const float wx = ix - fx0, wy = iy - fy0;
    const int x0 = (int)fx0, y0 = (int)fy0;

    float lc[32];
#pragma unroll
    for (int c = 0; c < 32; ++c) lc[c] = 0.f;

    const float cw[4] = { (1.f-wy)*(1.f-wx), (1.f-wy)*wx, wy*(1.f-wx), wy*wx };
    const int   cx[4] = { x0, x0 + 1, x0,     x0 + 1 };
    const int   cy[4] = { y0, y0,     y0 + 1, y0 + 1 };
#pragma unroll
    for (int cn = 0; cn < 4; ++cn) {
        const int xx = cx[cn], yy = cy[cn];
        if (xx >= 0 && xx < 16 && yy >= 0 && yy < 16) {
            const float4* cp = (const float4*)(g_comp + (b * 256 + yy * 16 + xx) * 32);
            const float w = cw[cn];
#pragma unroll
            for (int c4 = 0; c4 < 8; ++c4) {
                float4 v = cp[c4];
                lc[4*c4+0] = fmaf(w, v.x, lc[4*c4+0]);
                lc[4*c4+1] = fmaf(w, v.y, lc[4*c4+1]);
                lc[4*c4+2] = fmaf(w, v.z, lc[4*c4+2]);
                lc[4*c4+3] = fmaf(w, v.w, lc[4*c4+3]);
            }
        }
    }

    // vf: X' = vf_w @ concat(Xl[4], lc[32]) + vf_b
    float Xp[4];
#pragma unroll
    for (int j = 0; j < 4; ++j) {
        float s = __ldg(vf_b + j);
#pragma unroll
        for (int k = 0; k < 4; ++k)  s = fmaf(__ldg(vf_w + j*36 + k),     Xl[k], s);
#pragma unroll
        for (int c = 0; c < 32; ++c) s = fmaf(__ldg(vf_w + j*36 + 4 + c), lc[c], s);
        Xp[j] = s;
    }

    // Q (stored negated), K, V
#pragma unroll
    for (int d = 0; d < 8; ++d) {
        float qv = __ldg(fc_b + d);
#pragma unroll
        for (int k = 0; k < 4; ++k) qv = fmaf(__ldg(fc_w + d*4 + k), Xp[k], qv);
        g_Qn[m * 8 + d] = -qv;

        float kv = __ldg(fc2_b + d) + __ldg(fc2_w + 2*d) * xr0 + __ldg(fc2_w + 2*d + 1) * xr1;
        float vv = __ldg(fc3_b + d) + __ldg(fc3_w + 2*d) * xr0 + __ldg(fc3_w + 2*d + 1) * xr1;
        g_KV[m * 16 + d]     = kv;
        g_KV[m * 16 + 8 + d] = vv;
    }
}

// ---------------------------------------------------------------------------
// K3: sigmoid attention, split-K partials.
// grid (32 q-blocks, KSPLIT, B), block 256 (one query per thread).
// ---------------------------------------------------------------------------
__global__ void __launch_bounds__(256) k_attn()
{
    const int qb = blockIdx.x;
    const int ks = blockIdx.y;
    const int b  = blockIdx.z;
    const int q  = qb * 256 + threadIdx.x;
    const int m  = b * 8192 + q;

    __shared__ float4 sh[512 * 4];   // 512 keys x (K float4 x2 | V float4 x2)

    const float4 qa = *(const float4*)(g_Qn + m * 8);
    const float4 qc = *(const float4*)(g_Qn + m * 8 + 4);

    float acc[8];
#pragma unroll
    for (int d = 0; d < 8; ++d) acc[d] = 0.f;

    const int keys_per_split = TN / KSPLIT;   // 1024
    const int kbase = ks * keys_per_split;

    for (int tile = 0; tile < keys_per_split / 512; ++tile) {
        __syncthreads();
        const float4* src = (const float4*)(g_KV + (size_t)(b * 8192 + kbase + tile * 512) * 16);
#pragma unroll
        for (int i = 0; i < 8; ++i)
            sh[threadIdx.x + i * 256] = src[threadIdx.x + i * 256];
        __syncthreads();

#pragma unroll 4
        for (int k = 0; k < 512; ++k) {
            const float4 k0 = sh[k * 4 + 0];
            const float4 k1 = sh[k * 4 + 1];
            // dot(Qn, K) = -logit ; two chains for ILP
            float c0 = fmaf(qa.x, k0.x, fmaf(qa.z, k0.z, fmaf(qc.x, k1.x, qc.z * k1.z)));
            float c1 = fmaf(qa.y, k0.y, fmaf(qa.w, k0.w, fmaf(qc.y, k1.y, qc.w * k1.w)));
            const float e = __expf(c0 + c1);               // exp(-logit)
            const float s = __fdividef(1.f, 1.f + e);      // sigmoid(logit)
            const float4 v0 = sh[k * 4 + 2];
            const float4 v1 = sh[k * 4 + 3];
            acc[0] = fmaf(s, v0.x, acc[0]);
            acc[1] = fmaf(s, v0.y, acc[1]);
            acc[2] = fmaf(s, v0.z, acc[2]);
            acc[3] = fmaf(s, v0.w, acc[3]);
            acc[4] = fmaf(s, v1.x, acc[4]);
            acc[5] = fmaf(s, v1.y, acc[5]);
            acc[6] = fmaf(s, v1.z, acc[6]);
            acc[7] = fmaf(s, v1.w, acc[7]);
        }
    }

    float* op = g_att + ((size_t)ks * M_TOK + m) * 8;
    *(float4*)(op)     = make_float4(acc[0], acc[1], acc[2], acc[3]);
    *(float4*)(op + 4) = make_float4(acc[4], acc[5], acc[6], acc[7]);
}

// ---------------------------------------------------------------------------
// K4: reduce split-K, threshold-ReLU, fcout, write [B,2,T,N]
// ---------------------------------------------------------------------------
__global__ void __launch_bounds__(256) k_epilogue(
    float* __restrict__ out,
    const float* __restrict__ fcout_w, const float* __restrict__ fcout_b)
{
    const int m = blockIdx.x * blockDim.x + threadIdx.x;
    const int b = m >> 13;
    const int q = m & 8191;

    float o[8];
#pragma unroll
    for (int d = 0; d < 8; ++d) o[d] = 0.f;
#pragma unroll
    for (int ks = 0; ks < KSPLIT; ++ks) {
        const float4* p = (const float4*)(g_att + ((size_t)ks * M_TOK + m) * 8);
        float4 a = p[0], c = p[1];
        o[0] += a.x; o[1] += a.y; o[2] += a.z; o[3] += a.w;
        o[4] += c.x; o[5] += c.y; o[6] += c.z; o[7] += c.w;
    }
#pragma unroll
    for (int d = 0; d < 8; ++d) o[d] = (o[d] > 0.5f) ? o[d] : 0.f;

    float r0 = __ldg(fcout_b + 0);
    float r1 = __ldg(fcout_b + 1);
#pragma unroll
    for (int d = 0; d < 8; ++d) {
        r0 = fmaf(__ldg(fcout_w + d),     o[d], r0);
        r1 = fmaf(__ldg(fcout_w + 8 + d), o[d], r1);
    }
    out[b * 16384 + q]        = r0;   // channel 0
    out[b * 16384 + 8192 + q] = r1;   // channel 1
}

// ---------------------------------------------------------------------------
// Launch
// inputs: 0 x, 1 metadata, 2 w_ih, 3 w_hh(unused), 4 b_ih, 5 b_hh, 6 fc_w,
//         7 fc_b, 8 fc2_w, 9 fc2_b, 10 fc3_w, 11 fc3_b, 12 comp_w, 13 comp_b,
//         14 vf_w, 15 vf_b, 16 fcout_w, 17 fcout_b
// ---------------------------------------------------------------------------
extern "C" void kernel_launch(void* const* d_in, const int* in_sizes, int n_in,
                              void* d_out, int out_size)
{
    const float* x        = (const float*)d_in[0];
    const float* metadata = (const float*)d_in[1];
    const float* w_ih     = (const float*)d_in[2];
    const float* b_ih     = (const float*)d_in[4];
    const float* b_hh     = (const float*)d_in[5];
    const float* fc_w     = (const float*)d_in[6];
    const float* fc_b     = (const float*)d_in[7];
    const float* fc2_w    = (const float*)d_in[8];
    const float* fc2_b    = (const float*)d_in[9];
    const float* fc3_w    = (const float*)d_in[10];
    const float* fc3_b    = (const float*)d_in[11];
    const float* comp_w   = (const float*)d_in[12];
    const float* comp_b   = (const float*)d_in[13];
    const float* vf_w     = (const float*)d_in[14];
    const float* vf_b     = (const float*)d_in[15];
    const float* fcout_w  = (const float*)d_in[16];
    const float* fcout_b  = (const float*)d_in[17];
    float* out = (float*)d_out;

    k_comp_partial<<<dim3(NCHUNK, 2), 256>>>(metadata, comp_w);
    k_comp_reduce<<<64, 256>>>(comp_b);
    k_qkv<<<64, 256>>>(x, w_ih, b_ih, b_hh, fc_w, fc_b,
                       fc2_w, fc2_b, fc3_w, fc3_b, vf_w, vf_b);
    k_attn<<<dim3(32, KSPLIT, 2), 256>>>();
    k_epilogue<<<64, 256>>>(out, fcout_w, fcout_b);
}

// round 2
// speedup vs baseline: 2.6016x; 2.6016x over previous
#include <cuda_runtime.h>
#include <math.h>

// ---------------------------------------------------------------------------
// B=2, T=64, N=128 -> TN=8192, M=16384 ; IN_FEAT=2, H_LSTM=4, D=8
// FH=FW=16, C_MAP=2048, C_COMP=32, TH=0.5, IMG=512
//
// Rank-2 attention refactor:
//   K_k = W2·xr_k + b2 ; V_k = W3·xr_k + b3  (xr is 2-dim)
//   sigmoid(Q·K) = 0.5 + 0.5*tanh( A*xr0 + B*xr1 + C ),
//     A=0.5*Q·W2[:,0], B=0.5*Q·W2[:,1], C=0.5*Q·b2
//   out_q = 0.5*ΣV + 0.5*( S1*va + S2*vb + S0*vc ),
//     S0=Σt, S1=Σt*xr0, S2=Σt*xr1 ; ΣV = va*Σxr0 + vb*Σxr1 + 8192*vc
// ---------------------------------------------------------------------------
#define M_TOK   16384
#define TN      8192
#define KSPLIT  32      // 256 keys per split
#define NCHUNK  64      // channel chunks for comp conv (2048/32)

__device__ float  g_comp_part[NCHUNK * 16384];
__device__ float  g_comp[16384];                     // [b][pix256][oc32]
__device__ float4 g_ABC[M_TOK];                      // (A,B,C,0) per query
__device__ float2 g_XR[M_TOK];                       // xr per token (key data)
__device__ float2 g_sumxr[2];                        // per-batch Σxr
__device__ float4 g_att[(size_t)KSPLIT * M_TOK];     // (S0,S1,S2,0) partials

// ---------------- f32x2 helpers -------------------------------------------
using u64 = unsigned long long;
__device__ __forceinline__ u64 pack2(float lo, float hi) {
    u64 r; asm("mov.b64 %0,{%1,%2};" : "=l"(r) : "f"(lo), "f"(hi)); return r;
}
__device__ __forceinline__ void unpack2(u64 v, float& lo, float& hi) {
    asm("mov.b64 {%0,%1},%2;" : "=f"(lo), "=f"(hi) : "l"(v));
}
__device__ __forceinline__ u64 fma2(u64 a, u64 b, u64 c) {
    u64 d; asm("fma.rn.f32x2 %0,%1,%2,%3;" : "=l"(d) : "l"(a), "l"(b), "l"(c)); return d;
}
__device__ __forceinline__ u64 add2(u64 a, u64 b) {
    u64 d; asm("add.rn.f32x2 %0,%1,%2;" : "=l"(d) : "l"(a), "l"(b)); return d;
}
__device__ __forceinline__ float tanha(float x) {
    float r; asm("tanh.approx.f32 %0,%1;" : "=f"(r) : "f"(x)); return r;
}
__device__ __forceinline__ float sigf(float x) { return 1.f / (1.f + expf(-x)); }

// ---------------------------------------------------------------------------
// K1: comp partials. grid (NCHUNK, B), block 256 (one pixel each), 32 ch/chunk
// ---------------------------------------------------------------------------
__global__ void __launch_bounds__(256) k_comp_partial(
    const float* __restrict__ metadata, const float* __restrict__ comp_w)
{
    const int chunk = blockIdx.x, b = blockIdx.y, p = threadIdx.x;
    const int c0 = chunk * 32;

    __shared__ float sw[32 * 32];   // [oc][cl]
    for (int idx = threadIdx.x; idx < 1024; idx += 256) {
        int oc = idx >> 5, cl = idx & 31;
        sw[idx] = comp_w[oc * 2048 + c0 + cl];
    }
    __syncthreads();

    float acc[32];
#pragma unroll
    for (int oc = 0; oc < 32; ++oc) acc[oc] = 0.f;

    const float* mp = metadata + ((size_t)b * 2048 + c0) * 256 + p;
#pragma unroll 4
    for (int cl = 0; cl < 32; ++cl) {
        float mv = __ldg(mp + cl * 256);
#pragma unroll
        for (int oc = 0; oc < 32; ++oc)
            acc[oc] = fmaf(mv, sw[oc * 32 + cl], acc[oc]);
    }

    float4* op = (float4*)(g_comp_part + (size_t)chunk * 16384 + (b * 256 + p) * 32);
#pragma unroll
    for (int i = 0; i < 8; ++i)
        op[i] = make_float4(acc[4*i], acc[4*i+1], acc[4*i+2], acc[4*i+3]);
}

__global__ void __launch_bounds__(256) k_comp_reduce(const float* __restrict__ comp_b)
{
    int i = blockIdx.x * blockDim.x + threadIdx.x;
    float s = __ldg(comp_b + (i & 31));
#pragma unroll 8
    for (int ch = 0; ch < NCHUNK; ++ch)
        s += g_comp_part[(size_t)ch * 16384 + i];
    g_comp[i] = s;
}

// ---------------------------------------------------------------------------
// K2: per-token pipeline -> (A,B,C), xr
// ---------------------------------------------------------------------------
__global__ void __launch_bounds__(128) k_qkv(
    const float* __restrict__ x,
    const float* __restrict__ w_ih, const float* __restrict__ b_ih,
    const float* __restrict__ b_hh,
    const float* __restrict__ fc_w,  const float* __restrict__ fc_b,
    const float* __restrict__ fc2_w, const float* __restrict__ fc2_b,
    const float* __restrict__ vf_w,  const float* __restrict__ vf_b)
{
    const int m = blockIdx.x * blockDim.x + threadIdx.x;
    const int b = m >> 13;
    const int q = m & 8191;
    const int t = q >> 7;

    const float px = __ldg(x + b * 16384 + q);
    const float py = __ldg(x + b * 16384 + 8192 + q);

    const float xr0 = px + sinf((float)t);
    const float xr1 = py + cosf((float)t);

    // single-step LSTM (h0=c0=0), gates i,f,g,o
    float Xl[4];
#pragma unroll
    for (int j = 0; j < 4; ++j) {
        float gi = __ldg(w_ih + 2*j)      * xr0 + __ldg(w_ih + 2*j+1)      * xr1 + __ldg(b_ih + j)      + __ldg(b_hh + j);
        float gg = __ldg(w_ih + 2*(8+j))  * xr0 + __ldg(w_ih + 2*(8+j)+1)  * xr1 + __ldg(b_ih + 8 + j)  + __ldg(b_hh + 8 + j);
        float go = __ldg(w_ih + 2*(12+j)) * xr0 + __ldg(w_ih + 2*(12+j)+1) * xr1 + __ldg(b_ih + 12 + j) + __ldg(b_hh + 12 + j);
        float cst = sigf(gi) * tanhf(gg);
        Xl[j] = sigf(go) * tanhf(cst);
    }

    // bilinear grid-sample of g_comp
    const float ix = px * (1.f / 32.f) - 0.5f;
    const float iy = py * (1.f / 32.f) - 0.5f;
    const float fx0 = floorf(ix), fy0 = floorf(iy);
    const float wx = ix - fx0, wy = iy - fy0;
    const int x0 = (int)fx0, y0 = (int)fy0;

    float lc[32];
#pragma unroll
    for (int c = 0; c < 32; ++c) lc[c] = 0.f;

    const float cw[4] = { (1.f-wy)*(1.f-wx), (1.f-wy)*wx, wy*(1.f-wx), wy*wx };
    const int   cx[4] = { x0, x0 + 1, x0,     x0 + 1 };
    const int   cy[4] = { y0, y0,     y0 + 1, y0 + 1 };
#pragma unroll
    for (int cn = 0; cn < 4; ++cn) {
        const int xx = cx[cn], yy = cy[cn];
        if (xx >= 0 && xx < 16 && yy >= 0 && yy < 16) {
            const float4* cp = (const float4*)(g_comp + (b * 256 + yy * 16 + xx) * 32);
            const float w = cw[cn];
#pragma unroll
            for (int c4 = 0; c4 < 8; ++c4) {
                float4 v = cp[c4];
                lc[4*c4+0] = fmaf(w, v.x, lc[4*c4+0]);
                lc[4*c4+1] = fmaf(w, v.y, lc[4*c4+1]);
                lc[4*c4+2] = fmaf(w, v.z, lc[4*c4+2]);
                lc[4*c4+3] = fmaf(w, v.w, lc[4*c4+3]);
            }
        }
    }

    // vf fusion
    float Xp[4];
#pragma unroll
    for (int j = 0; j < 4; ++j) {
        float s = __ldg(vf_b + j);
#pragma unroll
        for (int k = 0; k < 4; ++k)  s = fmaf(__ldg(vf_w + j*36 + k),     Xl[k], s);
#pragma unroll
        for (int c = 0; c < 32; ++c) s = fmaf(__ldg(vf_w + j*36 + 4 + c), lc[c], s);
        Xp[j] = s;
    }

    // Q then rank-2 contraction vs K's affine map
    float A = 0.f, Bv = 0.f, Cv = 0.f;
#pragma unroll
    for (int d = 0; d < 8; ++d) {
        float qd = __ldg(fc_b + d);
#pragma unroll
        for (int k = 0; k < 4; ++k) qd = fmaf(__ldg(fc_w + d*4 + k), Xp[k], qd);
        A  = fmaf(qd, __ldg(fc2_w + 2*d),     A);
        Bv = fmaf(qd, __ldg(fc2_w + 2*d + 1), Bv);
        Cv = fmaf(qd, __ldg(fc2_b + d),       Cv);
    }
    g_ABC[m] = make_float4(0.5f * A, 0.5f * Bv, 0.5f * Cv, 0.f);
    g_XR[m]  = make_float2(xr0, xr1);
}

// ---------------------------------------------------------------------------
// K2b: per-batch Σxr (deterministic)
// ---------------------------------------------------------------------------
__global__ void __launch_bounds__(256) k_sumxr()
{
    const int b = blockIdx.x;
    __shared__ float2 sh[256];
    float s0 = 0.f, s1 = 0.f;
    for (int i = threadIdx.x; i < TN; i += 256) {
        float2 v = g_XR[b * TN + i];
        s0 += v.x; s1 += v.y;
    }
    sh[threadIdx.x] = make_float2(s0, s1);
    __syncthreads();
    for (int off = 128; off > 0; off >>= 1) {
        if (threadIdx.x < off) {
            sh[threadIdx.x].x += sh[threadIdx.x + off].x;
            sh[threadIdx.x].y += sh[threadIdx.x + off].y;
        }
        __syncthreads();
    }
    if (threadIdx.x == 0) g_sumxr[b] = sh[0];
}

// ---------------------------------------------------------------------------
// K3: attention. grid (16 qgroups, KSPLIT), block 128.
// Each thread: 8 queries (4 f32x2 pairs) x 256 keys.
// ---------------------------------------------------------------------------
__global__ void __launch_bounds__(128) k_attn()
{
    const int g  = blockIdx.x;            // 0..15 (8 per batch)
    const int ks = blockIdx.y;            // 0..31
    const int b  = g >> 3;
    const int kbase = b * TN + ks * 256;

    __shared__ float2 s_xr[256];
    s_xr[threadIdx.x]       = g_XR[kbase + threadIdx.x];
    s_xr[threadIdx.x + 128] = g_XR[kbase + threadIdx.x + 128];

    const int m0 = g * 1024 + threadIdx.x * 8;

    u64 A[4], Bv[4], C[4], S0[4], S1[4], S2[4];
#pragma unroll
    for (int p = 0; p < 4; ++p) {
        float4 a0 = g_ABC[m0 + 2*p];
        float4 a1 = g_ABC[m0 + 2*p + 1];
        A[p]  = pack2(a0.x, a1.x);
        Bv[p] = pack2(a0.y, a1.y);
        C[p]  = pack2(a0.z, a1.z);
        S0[p] = 0ull; S1[p] = 0ull; S2[p] = 0ull;
    }
    __syncthreads();

#pragma unroll 2
    for (int k = 0; k < 256; ++k) {
        const float2 xr = s_xr[k];
        const u64 x0 = pack2(xr.x, xr.x);
        const u64 x1 = pack2(xr.y, xr.y);
#pragma unroll
        for (int p = 0; p < 4; ++p) {
            u64 l = fma2(A[p], x0, fma2(Bv[p], x1, C[p]));
            float l0, l1; unpack2(l, l0, l1);
            const u64 t = pack2(tanha(l0), tanha(l1));
            S0[p] = add2(S0[p], t);
            S1[p] = fma2(t, x0, S1[p]);
            S2[p] = fma2(t, x1, S2[p]);
        }
    }

    float4* op = g_att + (size_t)ks * M_TOK + m0;
#pragma unroll
    for (int p = 0; p < 4; ++p) {
        float a0, a1, b0, b1, c0, c1;
        unpack2(S0[p], a0, a1); unpack2(S1[p], b0, b1); unpack2(S2[p], c0, c1);
        op[2*p]     = make_float4(a0, b0, c0, 0.f);
        op[2*p + 1] = make_float4(a1, b1, c1, 0.f);
    }
}

// ---------------------------------------------------------------------------
// K4: reduce splits, reconstruct out8, threshold, fcout
// ---------------------------------------------------------------------------
__global__ void __launch_bounds__(256) k_epilogue(
    float* __restrict__ out,
    const float* __restrict__ fc3_w, const float* __restrict__ fc3_b,
    const float* __restrict__ fcout_w, const float* __restrict__ fcout_b)
{
    const int m = blockIdx.x * blockDim.x + threadIdx.x;
    const int b = m >> 13;
    const int q = m & 8191;

    float S0 = 0.f, S1 = 0.f, S2 = 0.f;
#pragma unroll
    for (int ks = 0; ks < KSPLIT; ++ks) {
        float4 p = g_att[(size_t)ks * M_TOK + m];
        S0 += p.x; S1 += p.y; S2 += p.z;
    }
    const float2 sx = g_sumxr[b];
    const float f1 = 0.5f * (sx.x + S1);
    const float f2 = 0.5f * (sx.y + S2);
    const float f0 = 0.5f * ((float)TN + S0);

    float r0 = __ldg(fcout_b + 0);
    float r1 = __ldg(fcout_b + 1);
#pragma unroll
    for (int d = 0; d < 8; ++d) {
        float o = f1 * __ldg(fc3_w + 2*d) + f2 * __ldg(fc3_w + 2*d + 1)
                + f0 * __ldg(fc3_b + d);
        o = (o > 0.5f) ? o : 0.f;
        r0 = fmaf(__ldg(fcout_w + d),     o, r0);
        r1 = fmaf(__ldg(fcout_w + 8 + d), o, r1);
    }
    out[b * 16384 + q]        = r0;
    out[b * 16384 + 8192 + q] = r1;
}

// ---------------------------------------------------------------------------
extern "C" void kernel_launch(void* const* d_in, const int* in_sizes, int n_in,
                              void* d_out, int out_size)
{
    const float* x        = (const float*)d_in[0];
    const float* metadata = (const float*)d_in[1];
    const float* w_ih     = (const float*)d_in[2];
    const float* b_ih     = (const float*)d_in[4];
    const float* b_hh     = (const float*)d_in[5];
    const float* fc_w     = (const float*)d_in[6];
    const float* fc_b     = (const float*)d_in[7];
    const float* fc2_w    = (const float*)d_in[8];
    const float* fc2_b    = (const float*)d_in[9];
    const float* fc3_w    = (const float*)d_in[10];
    const float* fc3_b    = (const float*)d_in[11];
    const float* comp_w   = (const float*)d_in[12];
    const float* comp_b   = (const float*)d_in[13];
    const float* vf_w     = (const float*)d_in[14];
    const float* vf_b     = (const float*)d_in[15];
    const float* fcout_w  = (const float*)d_in[16];
    const float* fcout_b  = (const float*)d_in[17];
    float* out = (float*)d_out;

    k_comp_partial<<<dim3(NCHUNK, 2), 256>>>(metadata, comp_w);
    k_comp_reduce<<<64, 256>>>(comp_b);
    k_qkv<<<128, 128>>>(x, w_ih, b_ih, b_hh, fc_w, fc_b,
                        fc2_w, fc2_b, vf_w, vf_b);
    k_sumxr<<<2, 256>>>();
    k_attn<<<dim3(16, KSPLIT), 128>>>();
    k_epilogue<<<64, 256>>>(out, fc3_w, fc3_b, fcout_w, fcout_b);
}